// round 2
// baseline (speedup 1.0000x reference)
#include <cuda_runtime.h>
#include <cuda_bf16.h>
#include <math_constants.h>

// Problem dims
#define BATCH   256
#define CIN     512
#define KHW     49          // 7*7
#define KDIM    25088       // 512*49
#define COUT    1000
#define NPAD    1024        // padded C_out for scratch
#define KSPLIT  4
#define KSEG    (KDIM / KSPLIT)   // 6272
#define KC      8

#define HWPAD   52          // 49 padded to multiple of 4
#define SPD_SMEM (2 * CIN * HWPAD * 4)   // 212992 bytes

// Scratch (device globals only — no runtime allocation allowed)
__device__ float g_partial[KSPLIT * BATCH * NPAD];   // 4 MB
__device__ int   g_top2[BATCH * 2];

// ---------------------------------------------------------------------------
// Kernel 1: split-K GEMM partials.  part[ks][m][n] = sum_{k in seg} A[m,k]*W[n,k]
// grid (16 ntiles, 4 mtiles, 4 ksplit), 256 threads, 64x64 tile, 4x4 per thread
// ---------------------------------------------------------------------------
__global__ __launch_bounds__(256) void gemm_partial_kernel(
    const float* __restrict__ A,   // [256, 25088]
    const float* __restrict__ W)   // [1000, 25088]
{
    const int n0 = blockIdx.x * 64;
    const int m0 = blockIdx.y * 64;
    const int k0 = blockIdx.z * KSEG;

    __shared__ float As[KC][64];
    __shared__ float Bs[KC][64];

    const int tid = threadIdx.x;
    const int tx = tid & 15;        // n dir
    const int ty = tid >> 4;        // m dir

    // loader role: tid<128 loads A tile, tid>=128 loads B tile
    const bool isB = tid >= 128;
    const int lrow = (tid & 127) >> 1;   // 0..63
    const int lf4  = tid & 1;            // which float4 in the 8-wide k chunk

    const float* gptr;
    bool valid = true;
    if (!isB) {
        gptr = A + (size_t)(m0 + lrow) * KDIM;
    } else {
        int n = n0 + lrow;
        valid = (n < COUT);
        gptr = W + (size_t)(valid ? n : 0) * KDIM;
    }

    float acc[4][4];
#pragma unroll
    for (int i = 0; i < 4; i++)
#pragma unroll
        for (int j = 0; j < 4; j++) acc[i][j] = 0.f;

    for (int kb = k0; kb < k0 + KSEG; kb += KC) {
        float4 v = *(const float4*)(gptr + kb + lf4 * 4);
        if (isB && !valid) v = make_float4(0.f, 0.f, 0.f, 0.f);

        __syncthreads();   // previous compute done before smem overwrite
        float* dst = isB ? &Bs[0][0] : &As[0][0];
        dst[(lf4 * 4 + 0) * 64 + lrow] = v.x;
        dst[(lf4 * 4 + 1) * 64 + lrow] = v.y;
        dst[(lf4 * 4 + 2) * 64 + lrow] = v.z;
        dst[(lf4 * 4 + 3) * 64 + lrow] = v.w;
        __syncthreads();

#pragma unroll
        for (int kk = 0; kk < KC; kk++) {
            float4 a = *(const float4*)&As[kk][ty * 4];
            float4 b = *(const float4*)&Bs[kk][tx * 4];
            float av[4] = {a.x, a.y, a.z, a.w};
            float bv[4] = {b.x, b.y, b.z, b.w};
#pragma unroll
            for (int i = 0; i < 4; i++)
#pragma unroll
                for (int j = 0; j < 4; j++)
                    acc[i][j] += av[i] * bv[j];
        }
    }

    float* part = &g_partial[(size_t)blockIdx.z * BATCH * NPAD];
#pragma unroll
    for (int i = 0; i < 4; i++) {
        int m = m0 + ty * 4 + i;
#pragma unroll
        for (int j = 0; j < 4; j++) {
            int n = n0 + tx * 4 + j;
            part[(size_t)m * NPAD + n] = acc[i][j];
        }
    }
}

// ---------------------------------------------------------------------------
// Kernel 2: reduce split-K partials + bias -> outR (d_out[0:256000])
// ---------------------------------------------------------------------------
__global__ void reduce_bias_kernel(const float* __restrict__ bias,
                                   float* __restrict__ outR)
{
    int i = blockIdx.x * blockDim.x + threadIdx.x;
    if (i >= BATCH * COUT) return;
    int m = i / COUT;
    int n = i - m * COUT;
    float s = bias[n];
#pragma unroll
    for (int ks = 0; ks < KSPLIT; ks++)
        s += g_partial[(size_t)ks * BATCH * NPAD + (size_t)m * NPAD + n];
    outR[i] = s;
}

// ---------------------------------------------------------------------------
// Kernel 3: top-2 indices per sample (matches jax top_k: first occurrence wins)
// ---------------------------------------------------------------------------
__global__ void top2_kernel(const float* __restrict__ outR)
{
    const int n = blockIdx.x;
    const int tid = threadIdx.x;          // 128 threads
    float v1 = -CUDART_INF_F, v2 = -CUDART_INF_F;
    int   i1 = 0x7fffffff,   i2 = 0x7fffffff;

    for (int j = tid; j < COUT; j += 128) {
        float v = outR[n * COUT + j];
        if (v > v1 || (v == v1 && j < i1)) {
            v2 = v1; i2 = i1; v1 = v; i1 = j;
        } else if (v > v2 || (v == v2 && j < i2)) {
            v2 = v; i2 = j;
        }
    }

    __shared__ float sv1[128], sv2[128];
    __shared__ int   si1[128], si2[128];
    sv1[tid] = v1; si1[tid] = i1; sv2[tid] = v2; si2[tid] = i2;
    __syncthreads();

    for (int s = 64; s > 0; s >>= 1) {
        if (tid < s) {
            float a1 = sv1[tid],   a2 = sv2[tid];
            int   b1 = si1[tid],   b2 = si2[tid];
            float w1 = sv1[tid+s], w2 = sv2[tid+s];
            int   j1 = si1[tid+s], j2 = si2[tid+s];
            float r1, r2; int q1, q2;
            if (w1 > a1 || (w1 == a1 && j1 < b1)) {
                r1 = w1; q1 = j1;
                if (a1 > w2 || (a1 == w2 && b1 < j2)) { r2 = a1; q2 = b1; }
                else                                   { r2 = w2; q2 = j2; }
            } else {
                r1 = a1; q1 = b1;
                if (w1 > a2 || (w1 == a2 && j1 < b2)) { r2 = w1; q2 = j1; }
                else                                   { r2 = a2; q2 = b2; }
            }
            sv1[tid] = r1; si1[tid] = q1; sv2[tid] = r2; si2[tid] = q2;
        }
        __syncthreads();
    }
    if (tid == 0) {
        g_top2[n * 2 + 0] = si1[0];
        g_top2[n * 2 + 1] = si2[0];
    }
}

// ---------------------------------------------------------------------------
// Kernel 4: SPD path.  One block per sample n.
// outSPD[n,k,m] = sum_{c,hw} A_m[c,hw] * (sum_d SPD[n,c,d] * A_k[d,hw])
// A_k = weight[top2[n,k]] viewed as [512, 49], padded to 52 cols in smem.
// Each thread owns c = tid and c = tid + 256.
// ---------------------------------------------------------------------------
__global__ __launch_bounds__(256, 1) void spd_kernel(
    const float* __restrict__ SPD,   // [256, 512, 512]
    const float* __restrict__ W,     // [1000, 25088]
    float* __restrict__ outSPD)      // d_out + 256000, [256,2,2]
{
    extern __shared__ float sA[];    // A0[512][52] then A1[512][52]
    float* A0 = sA;
    float* A1 = sA + CIN * HWPAD;

    const int n = blockIdx.x;
    const int tid = threadIdx.x;

    const int o0 = g_top2[n * 2 + 0];
    const int o1 = g_top2[n * 2 + 1];
    const float* w0 = W + (size_t)o0 * KDIM;
    const float* w1 = W + (size_t)o1 * KDIM;

    // cooperative load of A0, A1 with zero padding (cols 49..51)
    for (int i = tid; i < CIN * HWPAD; i += 256) {
        int d  = i / HWPAD;
        int hw = i - d * HWPAD;
        float x0 = 0.f, x1 = 0.f;
        if (hw < KHW) {
            x0 = w0[d * KHW + hw];
            x1 = w1[d * KHW + hw];
        }
        A0[i] = x0;
        A1[i] = x1;
    }
    __syncthreads();

    float acc00 = 0.f, acc01 = 0.f, acc10 = 0.f, acc11 = 0.f;

#pragma unroll 1
    for (int cc = 0; cc < 2; cc++) {
        const int c = tid + cc * 256;
        float4 u0[13], u1[13];
#pragma unroll
        for (int i = 0; i < 13; i++) {
            u0[i] = make_float4(0.f, 0.f, 0.f, 0.f);
            u1[i] = make_float4(0.f, 0.f, 0.f, 0.f);
        }

        const float4* spdr = (const float4*)(SPD + (size_t)n * CIN * CIN + (size_t)c * CIN);

#pragma unroll 1
        for (int d4 = 0; d4 < CIN / 4; d4++) {
            float4 s = __ldg(&spdr[d4]);
            float sv[4] = {s.x, s.y, s.z, s.w};
#pragma unroll
            for (int j = 0; j < 4; j++) {
                const float4* a0r = (const float4*)&A0[(d4 * 4 + j) * HWPAD];
                const float4* a1r = (const float4*)&A1[(d4 * 4 + j) * HWPAD];
#pragma unroll
                for (int i = 0; i < 13; i++) {
                    float4 a = a0r[i];
                    u0[i].x += sv[j] * a.x;
                    u0[i].y += sv[j] * a.y;
                    u0[i].z += sv[j] * a.z;
                    u0[i].w += sv[j] * a.w;
                    float4 b = a1r[i];
                    u1[i].x += sv[j] * b.x;
                    u1[i].y += sv[j] * b.y;
                    u1[i].z += sv[j] * b.z;
                    u1[i].w += sv[j] * b.w;
                }
            }
        }

        // dot u_k (this c's slice of U_k) with A_m row c
        const float4* am0 = (const float4*)&A0[c * HWPAD];
        const float4* am1 = (const float4*)&A1[c * HWPAD];
        float d00 = 0.f, d01 = 0.f, d10 = 0.f, d11 = 0.f;
#pragma unroll
        for (int i = 0; i < 13; i++) {
            float4 a = am0[i];
            float4 b = am1[i];
            d00 += u0[i].x * a.x + u0[i].y * a.y + u0[i].z * a.z + u0[i].w * a.w;
            d01 += u0[i].x * b.x + u0[i].y * b.y + u0[i].z * b.z + u0[i].w * b.w;
            d10 += u1[i].x * a.x + u1[i].y * a.y + u1[i].z * a.z + u1[i].w * a.w;
            d11 += u1[i].x * b.x + u1[i].y * b.y + u1[i].z * b.z + u1[i].w * b.w;
        }
        acc00 += d00; acc01 += d01; acc10 += d10; acc11 += d11;
    }

    // block reduction of the 4 accumulators (reuse smem)
    __syncthreads();
    float* red = sA;   // needs 4*256 floats, smem is big enough
    red[0 * 256 + tid] = acc00;
    red[1 * 256 + tid] = acc01;
    red[2 * 256 + tid] = acc10;
    red[3 * 256 + tid] = acc11;
    __syncthreads();
    for (int s = 128; s > 0; s >>= 1) {
        if (tid < s) {
#pragma unroll
            for (int q = 0; q < 4; q++)
                red[q * 256 + tid] += red[q * 256 + tid + s];
        }
        __syncthreads();
    }
    if (tid == 0) {
        outSPD[n * 4 + 0] = red[0];        // k=0,m=0
        outSPD[n * 4 + 1] = red[256];      // k=0,m=1
        outSPD[n * 4 + 2] = red[512];      // k=1,m=0
        outSPD[n * 4 + 3] = red[768];      // k=1,m=1
    }
}

// ---------------------------------------------------------------------------
extern "C" void kernel_launch(void* const* d_in, const int* in_sizes, int n_in,
                              void* d_out, int out_size)
{
    const float* inputR   = (const float*)d_in[0];   // [256,512,7,7]
    const float* inputSPD = (const float*)d_in[1];   // [256,512,512]
    const float* weight   = (const float*)d_in[2];   // [1000,512,7,7]
    const float* bias     = (const float*)d_in[3];   // [1000]
    float* out = (float*)d_out;

    // opt-in to 208 KB dynamic smem for the SPD kernel (idempotent, host-side)
    cudaFuncSetAttribute(spd_kernel,
                         cudaFuncAttributeMaxDynamicSharedMemorySize, SPD_SMEM);

    // 1) split-K GEMM partials
    gemm_partial_kernel<<<dim3(16, 4, KSPLIT), 256>>>(inputR, weight);

    // 2) reduce + bias -> outputR
    reduce_bias_kernel<<<(BATCH * COUT + 255) / 256, 256>>>(bias, out);

    // 3) top-2 channel selection
    top2_kernel<<<BATCH, 128>>>(out);

    // 4) SPD path -> outputSPD at d_out + 256000
    spd_kernel<<<BATCH, 256, SPD_SMEM>>>(inputSPD, weight, out + BATCH * COUT);
}

// round 4
// speedup vs baseline: 1.8698x; 1.8698x over previous
#include <cuda_runtime.h>
#include <cuda_bf16.h>
#include <math_constants.h>
#include <cstdint>

// Problem dims
#define BATCH   256
#define CIN     512
#define KHW     49
#define KD      25088        // 512*49
#define COUT    1000
#define NPAD    1024
#define KSPLIT  16
#define KSEG    (KD / KSPLIT)     // 1568
#define NCHUNK  (KSEG / 16)       // 98

// Scratch (device globals only)
__device__ float g_partial[KSPLIT * BATCH * NPAD];   // 16.8 MB
__device__ int   g_top2[BATCH * 2];
__device__ float g_spd_part[BATCH * 4 * 4];          // [n][dt][4]

// ---------------------------------------------------------------------------
// bf16 split + mma helpers
// ---------------------------------------------------------------------------
__device__ __forceinline__ void bsplit(float v, __nv_bfloat16& h, __nv_bfloat16& l) {
    h = __float2bfloat16_rn(v);
    l = __float2bfloat16_rn(v - __bfloat162float(h));
}

__device__ __forceinline__ void mma16816(float* d, const unsigned* a, const unsigned* b) {
    asm volatile(
        "mma.sync.aligned.m16n8k16.row.col.f32.bf16.bf16.f32 "
        "{%0,%1,%2,%3}, {%4,%5,%6,%7}, {%8,%9}, {%0,%1,%2,%3};\n"
        : "+f"(d[0]), "+f"(d[1]), "+f"(d[2]), "+f"(d[3])
        : "r"(a[0]), "r"(a[1]), "r"(a[2]), "r"(a[3]), "r"(b[0]), "r"(b[1]));
}

#define U32S(p) (*reinterpret_cast<const unsigned*>(p))

// ---------------------------------------------------------------------------
// Kernel 1: FC GEMM, bf16-split mma.  part[ks][m][n] = sum_k A[m,k]*W[n,k]
// grid (8 ntiles, 2 mtiles, 16 ksplit), 256 thr, tile 128x128, BK=16
// warps 2(m) x 4(n): warp = 64m x 32n = 4 x 4 m16n8 frag tiles
// ---------------------------------------------------------------------------
#define ASTR 24   // smem row stride in bf16 for 16-wide k rows (conflict-free)

__global__ __launch_bounds__(256) void gemm_mma_kernel(
    const float* __restrict__ A, const float* __restrict__ W)
{
    __shared__ __nv_bfloat16 sAh[128 * ASTR], sAl[128 * ASTR];
    __shared__ __nv_bfloat16 sWh[128 * ASTR], sWl[128 * ASTR];

    const int t    = threadIdx.x;
    const int lane = t & 31, wid = t >> 5;
    const int wm = wid >> 2, wn = wid & 3;
    const int g = lane >> 2, tg = lane & 3;

    const int n0 = blockIdx.x * 128;
    const int m0 = blockIdx.y * 128;
    const int k0 = blockIdx.z * KSEG;

    // loader decomposition: 512 float4 per matrix, 2 per thread
    int lrow[2], lkq[2];
    bool wv[2];
#pragma unroll
    for (int i = 0; i < 2; i++) {
        int idx = t + i * 256;
        lrow[i] = idx >> 2;
        lkq[i]  = idx & 3;
        wv[i]   = (n0 + lrow[i]) < COUT;
    }

    float acc[4][4][4];
#pragma unroll
    for (int a = 0; a < 4; a++)
#pragma unroll
        for (int b = 0; b < 4; b++)
#pragma unroll
            for (int c = 0; c < 4; c++) acc[a][b][c] = 0.f;

    float4 pa[2], pw[2];
#pragma unroll
    for (int i = 0; i < 2; i++) {
        pa[i] = *(const float4*)(A + (size_t)(m0 + lrow[i]) * KD + k0 + lkq[i] * 4);
        pw[i] = wv[i] ? *(const float4*)(W + (size_t)(n0 + lrow[i]) * KD + k0 + lkq[i] * 4)
                      : make_float4(0.f, 0.f, 0.f, 0.f);
    }

    for (int c = 0; c < NCHUNK; c++) {
        __syncthreads();   // previous compute done before smem overwrite
#pragma unroll
        for (int i = 0; i < 2; i++) {
            const float av[4] = {pa[i].x, pa[i].y, pa[i].z, pa[i].w};
            const float wv4[4] = {pw[i].x, pw[i].y, pw[i].z, pw[i].w};
            int base = lrow[i] * ASTR + lkq[i] * 4;
#pragma unroll
            for (int j = 0; j < 4; j++) {
                __nv_bfloat16 h, l;
                bsplit(av[j], h, l);
                sAh[base + j] = h; sAl[base + j] = l;
                bsplit(wv4[j], h, l);
                sWh[base + j] = h; sWl[base + j] = l;
            }
        }
        __syncthreads();

        if (c + 1 < NCHUNK) {
            int kb = k0 + (c + 1) * 16;
#pragma unroll
            for (int i = 0; i < 2; i++) {
                pa[i] = *(const float4*)(A + (size_t)(m0 + lrow[i]) * KD + kb + lkq[i] * 4);
                pw[i] = wv[i] ? *(const float4*)(W + (size_t)(n0 + lrow[i]) * KD + kb + lkq[i] * 4)
                              : make_float4(0.f, 0.f, 0.f, 0.f);
            }
        }

        // B frags for all 4 n-tiles
        unsigned bh[4][2], bl[4][2];
#pragma unroll
        for (int ni = 0; ni < 4; ni++) {
            int nr = wn * 32 + ni * 8 + g;
            int base = nr * ASTR + tg * 2;
            bh[ni][0] = U32S(&sWh[base]);     bh[ni][1] = U32S(&sWh[base + 8]);
            bl[ni][0] = U32S(&sWl[base]);     bl[ni][1] = U32S(&sWl[base + 8]);
        }
#pragma unroll
        for (int mi = 0; mi < 4; mi++) {
            int mr = wm * 64 + mi * 16 + g;
            int base = mr * ASTR + tg * 2;
            unsigned ah[4], al[4];
            ah[0] = U32S(&sAh[base]);              ah[1] = U32S(&sAh[base + 8 * ASTR]);
            ah[2] = U32S(&sAh[base + 8]);          ah[3] = U32S(&sAh[base + 8 * ASTR + 8]);
            al[0] = U32S(&sAl[base]);              al[1] = U32S(&sAl[base + 8 * ASTR]);
            al[2] = U32S(&sAl[base + 8]);          al[3] = U32S(&sAl[base + 8 * ASTR + 8]);
#pragma unroll
            for (int ni = 0; ni < 4; ni++) {
                mma16816(acc[mi][ni], ah, bh[ni]);
                mma16816(acc[mi][ni], ah, bl[ni]);
                mma16816(acc[mi][ni], al, bh[ni]);
            }
        }
    }

    float* part = g_partial + (size_t)blockIdx.z * BATCH * NPAD;
#pragma unroll
    for (int mi = 0; mi < 4; mi++)
#pragma unroll
        for (int ni = 0; ni < 4; ni++)
#pragma unroll
            for (int v = 0; v < 4; v++) {
                int m = m0 + wm * 64 + mi * 16 + g + ((v >= 2) ? 8 : 0);
                int n = n0 + wn * 32 + ni * 8 + tg * 2 + (v & 1);
                part[(size_t)m * NPAD + n] = acc[mi][ni][v];
            }
}

// ---------------------------------------------------------------------------
// Kernel 2: reduce split-K partials + bias
// ---------------------------------------------------------------------------
__global__ void reduce_bias_kernel(const float* __restrict__ bias,
                                   float* __restrict__ outR)
{
    int i = blockIdx.x * blockDim.x + threadIdx.x;
    if (i >= BATCH * COUT) return;
    int m = i / COUT;
    int n = i - m * COUT;
    float s = bias[n];
#pragma unroll
    for (int ks = 0; ks < KSPLIT; ks++)
        s += g_partial[(size_t)ks * BATCH * NPAD + (size_t)m * NPAD + n];
    outR[i] = s;
}

// ---------------------------------------------------------------------------
// Kernel 3: top-2 indices per sample (first occurrence wins)
// ---------------------------------------------------------------------------
__global__ void top2_kernel(const float* __restrict__ outR)
{
    const int n = blockIdx.x;
    const int tid = threadIdx.x;
    float v1 = -CUDART_INF_F, v2 = -CUDART_INF_F;
    int   i1 = 0x7fffffff,   i2 = 0x7fffffff;

    for (int j = tid; j < COUT; j += 128) {
        float v = outR[n * COUT + j];
        if (v > v1 || (v == v1 && j < i1)) { v2 = v1; i2 = i1; v1 = v; i1 = j; }
        else if (v > v2 || (v == v2 && j < i2)) { v2 = v; i2 = j; }
    }

    __shared__ float sv1[128], sv2[128];
    __shared__ int   si1[128], si2[128];
    sv1[tid] = v1; si1[tid] = i1; sv2[tid] = v2; si2[tid] = i2;
    __syncthreads();

    for (int s = 64; s > 0; s >>= 1) {
        if (tid < s) {
            float a1 = sv1[tid],   a2 = sv2[tid];
            int   b1 = si1[tid],   b2 = si2[tid];
            float w1 = sv1[tid+s], w2 = sv2[tid+s];
            int   j1 = si1[tid+s], j2 = si2[tid+s];
            float r1, r2; int q1, q2;
            if (w1 > a1 || (w1 == a1 && j1 < b1)) {
                r1 = w1; q1 = j1;
                if (a1 > w2 || (a1 == w2 && b1 < j2)) { r2 = a1; q2 = b1; }
                else                                   { r2 = w2; q2 = j2; }
            } else {
                r1 = a1; q1 = b1;
                if (w1 > a2 || (w1 == a2 && j1 < b2)) { r2 = w1; q2 = j1; }
                else                                   { r2 = a2; q2 = b2; }
            }
            sv1[tid] = r1; si1[tid] = q1; sv2[tid] = r2; si2[tid] = q2;
        }
        __syncthreads();
    }
    if (tid == 0) {
        g_top2[n * 2 + 0] = si1[0];
        g_top2[n * 2 + 1] = si2[0];
    }
}

// ---------------------------------------------------------------------------
// Kernel 4: SPD path via Gram matrices and mma.
// out[k][m] = sum_{c,d} SPD[n][c][d] * G^{km}[d][c],  G^{km} = A_k A_m^T
// G^{km}[r][s] = sum_hw A_k[r][hw] * A_m[s][hw]  (K = hw = 49 pad 64)
// out[0][1] = <S_sr, G01>,  out[1][0] = <S_rs, G01>.
// Block = (n, dtile of 128 r).  Loops ct over 8 c-tiles of 64 s.
// Warps 2(r) x 4(s): warp = 64r x 16s = 4 x 2 frag tiles, 32 acc per G.
// ---------------------------------------------------------------------------
#define WSTR 72      // smem bf16 row stride for 64-wide rows (conflict-free)

// dynamic smem layout (bytes)
#define OFF_AD0H 0
#define OFF_AD0L (OFF_AD0H + 128 * WSTR * 2)
#define OFF_AD1H (OFF_AD0L + 128 * WSTR * 2)
#define OFF_AD1L (OFF_AD1H + 128 * WSTR * 2)
#define OFF_AC0H (OFF_AD1L + 128 * WSTR * 2)    // 73728
#define OFF_AC0L (OFF_AC0H + 64 * WSTR * 2)
#define OFF_AC1H (OFF_AC0L + 64 * WSTR * 2)
#define OFF_AC1L (OFF_AC1H + 64 * WSTR * 2)
#define OFF_SSR  (OFF_AC1L + 64 * WSTR * 2)     // 110592
#define SSR_STR  132
#define OFF_SRS  (OFF_SSR + 64 * SSR_STR * 4)   // 144384
#define SRS_STR  68
#define SPD_SMEM (OFF_SRS + 128 * SRS_STR * 4)  // 179200

__global__ __launch_bounds__(256) void spd_mma_kernel(
    const float* __restrict__ SPD, const float* __restrict__ W)
{
    extern __shared__ char sm[];
    __nv_bfloat16* Ad0h = (__nv_bfloat16*)(sm + OFF_AD0H);
    __nv_bfloat16* Ad0l = (__nv_bfloat16*)(sm + OFF_AD0L);
    __nv_bfloat16* Ad1h = (__nv_bfloat16*)(sm + OFF_AD1H);
    __nv_bfloat16* Ad1l = (__nv_bfloat16*)(sm + OFF_AD1L);
    __nv_bfloat16* Ac0h = (__nv_bfloat16*)(sm + OFF_AC0H);
    __nv_bfloat16* Ac0l = (__nv_bfloat16*)(sm + OFF_AC0L);
    __nv_bfloat16* Ac1h = (__nv_bfloat16*)(sm + OFF_AC1H);
    __nv_bfloat16* Ac1l = (__nv_bfloat16*)(sm + OFF_AC1L);
    float* Ssr = (float*)(sm + OFF_SSR);
    float* Srs = (float*)(sm + OFF_SRS);

    const int t = threadIdx.x;
    const int lane = t & 31, wid = t >> 5;
    const int wr = wid >> 2, ws = wid & 3;
    const int g = lane >> 2, tg = lane & 3;

    const int n  = blockIdx.y;
    const int d0 = blockIdx.x * 128;

    const int o0 = g_top2[n * 2 + 0];
    const int o1 = g_top2[n * 2 + 1];
    const float* w0 = W + (size_t)o0 * KD;
    const float* w1 = W + (size_t)o1 * KD;
    const float* Sn = SPD + (size_t)n * CIN * CIN;

    // Stage Ad (both weights, 128 rows from d0, 64 hw cols zero-padded)
#pragma unroll 4
    for (int i = 0; i < 32; i++) {
        int idx = t + i * 256;
        int r  = idx >> 6;
        int hw = idx & 63;
        float v0 = 0.f, v1 = 0.f;
        if (hw < KHW) {
            v0 = w0[(d0 + r) * KHW + hw];
            v1 = w1[(d0 + r) * KHW + hw];
        }
        __nv_bfloat16 h, l;
        bsplit(v0, h, l); Ad0h[r * WSTR + hw] = h; Ad0l[r * WSTR + hw] = l;
        bsplit(v1, h, l); Ad1h[r * WSTR + hw] = h; Ad1l[r * WSTR + hw] = l;
    }

    float p00 = 0.f, p01 = 0.f, p10 = 0.f, p11 = 0.f;

    for (int ct = 0; ct < 8; ct++) {
        const int c0 = ct * 64;
        __syncthreads();   // compute of prev iter done (also covers Ad staging)

        // Stage Ac (both weights, 64 rows from c0)
#pragma unroll 4
        for (int i = 0; i < 16; i++) {
            int idx = t + i * 256;
            int r  = idx >> 6;
            int hw = idx & 63;
            float v0 = 0.f, v1 = 0.f;
            if (hw < KHW) {
                v0 = w0[(c0 + r) * KHW + hw];
                v1 = w1[(c0 + r) * KHW + hw];
            }
            __nv_bfloat16 h, l;
            bsplit(v0, h, l); Ac0h[r * WSTR + hw] = h; Ac0l[r * WSTR + hw] = l;
            bsplit(v1, h, l); Ac1h[r * WSTR + hw] = h; Ac1l[r * WSTR + hw] = l;
        }
        // Stage S_sr[s][r] = SPD[c0+s][d0+r]   (64 x 128)
#pragma unroll 4
        for (int i = 0; i < 8; i++) {
            int idx = t + i * 256;      // 2048 float4
            int s  = idx >> 5;
            int rq = idx & 31;
            float4 v = *(const float4*)(Sn + (size_t)(c0 + s) * CIN + d0 + rq * 4);
            *(float4*)&Ssr[s * SSR_STR + rq * 4] = v;
        }
        // Stage S_rs[r][s] = SPD[d0+r][c0+s]   (128 x 64)
#pragma unroll 4
        for (int i = 0; i < 8; i++) {
            int idx = t + i * 256;
            int r  = idx >> 4;
            int sq = idx & 15;
            float4 v = *(const float4*)(Sn + (size_t)(d0 + r) * CIN + c0 + sq * 4);
            *(float4*)&Srs[r * SRS_STR + sq * 4] = v;
        }
        __syncthreads();

        // ---- pass 1: G0 = Ad0 x Ac0, G1 = Ad0 x Ac1 ----
        float acc0[4][2][4], acc1[4][2][4];
#pragma unroll
        for (int a = 0; a < 4; a++)
#pragma unroll
            for (int b = 0; b < 2; b++)
#pragma unroll
                for (int v = 0; v < 4; v++) { acc0[a][b][v] = 0.f; acc1[a][b][v] = 0.f; }

#pragma unroll
        for (int ks = 0; ks < 4; ks++) {
            const int kb = ks * 16;
            unsigned b0h[2][2], b0l[2][2], b1h[2][2], b1l[2][2];
#pragma unroll
            for (int ni = 0; ni < 2; ni++) {
                int cr = ws * 16 + ni * 8 + g;
                int base = cr * WSTR + kb + tg * 2;
                b0h[ni][0] = U32S(&Ac0h[base]); b0h[ni][1] = U32S(&Ac0h[base + 8]);
                b0l[ni][0] = U32S(&Ac0l[base]); b0l[ni][1] = U32S(&Ac0l[base + 8]);
                b1h[ni][0] = U32S(&Ac1h[base]); b1h[ni][1] = U32S(&Ac1h[base + 8]);
                b1l[ni][0] = U32S(&Ac1l[base]); b1l[ni][1] = U32S(&Ac1l[base + 8]);
            }
#pragma unroll
            for (int mi = 0; mi < 4; mi++) {
                int rr = wr * 64 + mi * 16 + g;
                int base = rr * WSTR + kb + tg * 2;
                unsigned ah[4], al[4];
                ah[0] = U32S(&Ad0h[base]);            ah[1] = U32S(&Ad0h[base + 8 * WSTR]);
                ah[2] = U32S(&Ad0h[base + 8]);        ah[3] = U32S(&Ad0h[base + 8 * WSTR + 8]);
                al[0] = U32S(&Ad0l[base]);            al[1] = U32S(&Ad0l[base + 8 * WSTR]);
                al[2] = U32S(&Ad0l[base + 8]);        al[3] = U32S(&Ad0l[base + 8 * WSTR + 8]);
#pragma unroll
                for (int ni = 0; ni < 2; ni++) {
                    mma16816(acc0[mi][ni], ah, b0h[ni]);
                    mma16816(acc0[mi][ni], ah, b0l[ni]);
                    mma16816(acc0[mi][ni], al, b0h[ni]);
                    mma16816(acc1[mi][ni], ah, b1h[ni]);
                    mma16816(acc1[mi][ni], ah, b1l[ni]);
                    mma16816(acc1[mi][ni], al, b1h[ni]);
                }
            }
        }
        // fold pass1 accumulators
#pragma unroll
        for (int mi = 0; mi < 4; mi++)
#pragma unroll
            for (int ni = 0; ni < 2; ni++)
#pragma unroll
                for (int v = 0; v < 4; v++) {
                    int r = wr * 64 + mi * 16 + g + ((v >= 2) ? 8 : 0);
                    int s = ws * 16 + ni * 8 + tg * 2 + (v & 1);
                    float ssr = Ssr[s * SSR_STR + r];
                    float srs = Srs[r * SRS_STR + s];
                    p00 += ssr * acc0[mi][ni][v];
                    p01 += ssr * acc1[mi][ni][v];
                    p10 += srs * acc1[mi][ni][v];
                }

        // ---- pass 2: G2 = Ad1 x Ac1 ----
        float acc2[4][2][4];
#pragma unroll
        for (int a = 0; a < 4; a++)
#pragma unroll
            for (int b = 0; b < 2; b++)
#pragma unroll
                for (int v = 0; v < 4; v++) acc2[a][b][v] = 0.f;

#pragma unroll
        for (int ks = 0; ks < 4; ks++) {
            const int kb = ks * 16;
            unsigned b1h[2][2], b1l[2][2];
#pragma unroll
            for (int ni = 0; ni < 2; ni++) {
                int cr = ws * 16 + ni * 8 + g;
                int base = cr * WSTR + kb + tg * 2;
                b1h[ni][0] = U32S(&Ac1h[base]); b1h[ni][1] = U32S(&Ac1h[base + 8]);
                b1l[ni][0] = U32S(&Ac1l[base]); b1l[ni][1] = U32S(&Ac1l[base + 8]);
            }
#pragma unroll
            for (int mi = 0; mi < 4; mi++) {
                int rr = wr * 64 + mi * 16 + g;
                int base = rr * WSTR + kb + tg * 2;
                unsigned ah[4], al[4];
                ah[0] = U32S(&Ad1h[base]);            ah[1] = U32S(&Ad1h[base + 8 * WSTR]);
                ah[2] = U32S(&Ad1h[base + 8]);        ah[3] = U32S(&Ad1h[base + 8 * WSTR + 8]);
                al[0] = U32S(&Ad1l[base]);            al[1] = U32S(&Ad1l[base + 8 * WSTR]);
                al[2] = U32S(&Ad1l[base + 8]);        al[3] = U32S(&Ad1l[base + 8 * WSTR + 8]);
#pragma unroll
                for (int ni = 0; ni < 2; ni++) {
                    mma16816(acc2[mi][ni], ah, b1h[ni]);
                    mma16816(acc2[mi][ni], ah, b1l[ni]);
                    mma16816(acc2[mi][ni], al, b1h[ni]);
                }
            }
        }
#pragma unroll
        for (int mi = 0; mi < 4; mi++)
#pragma unroll
            for (int ni = 0; ni < 2; ni++)
#pragma unroll
                for (int v = 0; v < 4; v++) {
                    int r = wr * 64 + mi * 16 + g + ((v >= 2) ? 8 : 0);
                    int s = ws * 16 + ni * 8 + tg * 2 + (v & 1);
                    p11 += Ssr[s * SSR_STR + r] * acc2[mi][ni][v];
                }
    }

    // block reduction of 4 scalars (reuse dynamic smem)
    __syncthreads();
    float* red = (float*)sm;    // 4 * 256 floats
    red[0 * 256 + t] = p00;
    red[1 * 256 + t] = p01;
    red[2 * 256 + t] = p10;
    red[3 * 256 + t] = p11;
    __syncthreads();
    for (int s = 128; s > 0; s >>= 1) {
        if (t < s) {
#pragma unroll
            for (int q = 0; q < 4; q++)
                red[q * 256 + t] += red[q * 256 + t + s];
        }
        __syncthreads();
    }
    if (t == 0) {
        int dt = blockIdx.x;
#pragma unroll
        for (int q = 0; q < 4; q++)
            g_spd_part[(n * 4 + dt) * 4 + q] = red[q * 256];
    }
}

// ---------------------------------------------------------------------------
// Kernel 5: reduce SPD partials over dtiles -> outSPD
// ---------------------------------------------------------------------------
__global__ void spd_reduce_kernel(float* __restrict__ outSPD)
{
    int i = blockIdx.x * 256 + threadIdx.x;
    if (i >= BATCH * 4) return;
    int n = i >> 2, q = i & 3;
    float s = 0.f;
#pragma unroll
    for (int dt = 0; dt < 4; dt++)
        s += g_spd_part[(n * 4 + dt) * 4 + q];
    outSPD[i] = s;
}

// ---------------------------------------------------------------------------
extern "C" void kernel_launch(void* const* d_in, const int* in_sizes, int n_in,
                              void* d_out, int out_size)
{
    const float* inputR   = (const float*)d_in[0];   // [256,512,7,7]
    const float* inputSPD = (const float*)d_in[1];   // [256,512,512]
    const float* weight   = (const float*)d_in[2];   // [1000,512,7,7]
    const float* bias     = (const float*)d_in[3];   // [1000]
    float* out = (float*)d_out;

    cudaFuncSetAttribute(spd_mma_kernel,
                         cudaFuncAttributeMaxDynamicSharedMemorySize, SPD_SMEM);

    // 1) FC GEMM (bf16-split tensor cores), split-K partials
    gemm_mma_kernel<<<dim3(8, 2, KSPLIT), 256>>>(inputR, weight);

    // 2) reduce + bias -> outputR
    reduce_bias_kernel<<<(BATCH * COUT + 255) / 256, 256>>>(bias, out);

    // 3) top-2 channel selection
    top2_kernel<<<BATCH, 128>>>(out);

    // 4) SPD path via Gram matrices + mma
    spd_mma_kernel<<<dim3(4, BATCH), 256, SPD_SMEM>>>(inputSPD, weight);

    // 5) reduce SPD partials
    spd_reduce_kernel<<<4, 256>>>(out + BATCH * COUT);
}

// round 5
// speedup vs baseline: 3.0302x; 1.6206x over previous
#include <cuda_runtime.h>
#include <cuda_bf16.h>
#include <math_constants.h>
#include <cstdint>

// Problem dims
#define BATCH   256
#define CIN     512
#define KHW     49
#define KD      25088        // 512*49
#define COUT    1000
#define NPAD    1024
#define KSPLIT  16
#define KSEG    (KD / KSPLIT)     // 1568
#define NCHUNK  (KSEG / 16)       // 98

// Scratch (device globals only)
__device__ float g_partial[KSPLIT * BATCH * NPAD];   // 16.8 MB
__device__ int   g_top2[BATCH * 2];
__device__ float g_spd_part[BATCH * 4 * 4];          // [n][dt][4]

// ---------------------------------------------------------------------------
// helpers
// ---------------------------------------------------------------------------
__device__ __forceinline__ void bsplit(float v, __nv_bfloat16& h, __nv_bfloat16& l) {
    h = __float2bfloat16_rn(v);
    l = __float2bfloat16_rn(v - __bfloat162float(h));
}

__device__ __forceinline__ void mma16816(float* d, const unsigned* a, const unsigned* b) {
    asm volatile(
        "mma.sync.aligned.m16n8k16.row.col.f32.bf16.bf16.f32 "
        "{%0,%1,%2,%3}, {%4,%5,%6,%7}, {%8,%9}, {%0,%1,%2,%3};\n"
        : "+f"(d[0]), "+f"(d[1]), "+f"(d[2]), "+f"(d[3])
        : "r"(a[0]), "r"(a[1]), "r"(a[2]), "r"(a[3]), "r"(b[0]), "r"(b[1]));
}

#define U32S(p) (*reinterpret_cast<const unsigned*>(p))

// ---------------------------------------------------------------------------
// Kernel 1: FC GEMM, bf16-split mma, double-buffered smem.
// part[ks][m][n] = sum_k A[m,k]*W[n,k]
// grid (8 ntiles, 2 mtiles, 16 ksplit), 256 thr, tile 128x128, BK=16
// warps 2(m) x 4(n): warp = 64m x 32n
// ---------------------------------------------------------------------------
#define ASTR 24                       // bf16 row stride
#define GTILE (128 * ASTR * 2)        // 6144 B per matrix-part
#define GSET  (4 * GTILE)             // Ah,Al,Wh,Wl per buffer = 24576
#define GEMM_SMEM (2 * GSET)          // 49152

__global__ __launch_bounds__(256) void gemm_mma_kernel(
    const float* __restrict__ A, const float* __restrict__ W)
{
    extern __shared__ char smraw[];

    const int t    = threadIdx.x;
    const int lane = t & 31, wid = t >> 5;
    const int wm = wid >> 2, wn = wid & 3;
    const int g = lane >> 2, tg = lane & 3;

    const int n0 = blockIdx.x * 128;
    const int m0 = blockIdx.y * 128;
    const int k0 = blockIdx.z * KSEG;

    int lrow[2], lkq[2];
    bool wvv[2];
#pragma unroll
    for (int i = 0; i < 2; i++) {
        int idx = t + i * 256;
        lrow[i] = idx >> 2;
        lkq[i]  = idx & 3;
        wvv[i]  = (n0 + lrow[i]) < COUT;
    }

    float acc[4][4][4];
#pragma unroll
    for (int a = 0; a < 4; a++)
#pragma unroll
        for (int b = 0; b < 4; b++)
#pragma unroll
            for (int c = 0; c < 4; c++) acc[a][b][c] = 0.f;

    float4 pa[2], pw[2];

    auto loadchunk = [&](int c) {
        int kb = k0 + c * 16;
#pragma unroll
        for (int i = 0; i < 2; i++) {
            pa[i] = *(const float4*)(A + (size_t)(m0 + lrow[i]) * KD + kb + lkq[i] * 4);
            pw[i] = wvv[i] ? *(const float4*)(W + (size_t)(n0 + lrow[i]) * KD + kb + lkq[i] * 4)
                           : make_float4(0.f, 0.f, 0.f, 0.f);
        }
    };
    auto storechunk = [&](int buf) {
        __nv_bfloat16* dAh = (__nv_bfloat16*)(smraw + buf * GSET + 0 * GTILE);
        __nv_bfloat16* dAl = (__nv_bfloat16*)(smraw + buf * GSET + 1 * GTILE);
        __nv_bfloat16* dWh = (__nv_bfloat16*)(smraw + buf * GSET + 2 * GTILE);
        __nv_bfloat16* dWl = (__nv_bfloat16*)(smraw + buf * GSET + 3 * GTILE);
#pragma unroll
        for (int i = 0; i < 2; i++) {
            const float av[4]  = {pa[i].x, pa[i].y, pa[i].z, pa[i].w};
            const float wv4[4] = {pw[i].x, pw[i].y, pw[i].z, pw[i].w};
            int base = lrow[i] * ASTR + lkq[i] * 4;
#pragma unroll
            for (int j = 0; j < 4; j++) {
                __nv_bfloat16 h, l;
                bsplit(av[j], h, l);  dAh[base + j] = h; dAl[base + j] = l;
                bsplit(wv4[j], h, l); dWh[base + j] = h; dWl[base + j] = l;
            }
        }
    };

    loadchunk(0);
    storechunk(0);
    loadchunk(1);
    __syncthreads();

    for (int c = 0; c < NCHUNK; c++) {
        if (c + 1 < NCHUNK) storechunk((c + 1) & 1);
        if (c + 2 < NCHUNK) loadchunk(c + 2);

        const __nv_bfloat16* sAh = (const __nv_bfloat16*)(smraw + (c & 1) * GSET + 0 * GTILE);
        const __nv_bfloat16* sAl = (const __nv_bfloat16*)(smraw + (c & 1) * GSET + 1 * GTILE);
        const __nv_bfloat16* sWh = (const __nv_bfloat16*)(smraw + (c & 1) * GSET + 2 * GTILE);
        const __nv_bfloat16* sWl = (const __nv_bfloat16*)(smraw + (c & 1) * GSET + 3 * GTILE);

        unsigned bh[4][2], bl[4][2];
#pragma unroll
        for (int ni = 0; ni < 4; ni++) {
            int nr = wn * 32 + ni * 8 + g;
            int base = nr * ASTR + tg * 2;
            bh[ni][0] = U32S(&sWh[base]);  bh[ni][1] = U32S(&sWh[base + 8]);
            bl[ni][0] = U32S(&sWl[base]);  bl[ni][1] = U32S(&sWl[base + 8]);
        }
#pragma unroll
        for (int mi = 0; mi < 4; mi++) {
            int mr = wm * 64 + mi * 16 + g;
            int base = mr * ASTR + tg * 2;
            unsigned ah[4], al[4];
            ah[0] = U32S(&sAh[base]);       ah[1] = U32S(&sAh[base + 8 * ASTR]);
            ah[2] = U32S(&sAh[base + 8]);   ah[3] = U32S(&sAh[base + 8 * ASTR + 8]);
            al[0] = U32S(&sAl[base]);       al[1] = U32S(&sAl[base + 8 * ASTR]);
            al[2] = U32S(&sAl[base + 8]);   al[3] = U32S(&sAl[base + 8 * ASTR + 8]);
#pragma unroll
            for (int ni = 0; ni < 4; ni++) {
                mma16816(acc[mi][ni], ah, bh[ni]);
                mma16816(acc[mi][ni], ah, bl[ni]);
                mma16816(acc[mi][ni], al, bh[ni]);
            }
        }
        __syncthreads();
    }

    float* part = g_partial + (size_t)blockIdx.z * BATCH * NPAD;
#pragma unroll
    for (int mi = 0; mi < 4; mi++)
#pragma unroll
        for (int ni = 0; ni < 4; ni++)
#pragma unroll
            for (int v = 0; v < 4; v++) {
                int m = m0 + wm * 64 + mi * 16 + g + ((v >= 2) ? 8 : 0);
                int n = n0 + wn * 32 + ni * 8 + tg * 2 + (v & 1);
                part[(size_t)m * NPAD + n] = acc[mi][ni][v];
            }
}

// ---------------------------------------------------------------------------
// Kernel 2: fused split-K reduce + bias + top-2.  One block per sample m.
// ---------------------------------------------------------------------------
__global__ __launch_bounds__(256) void reduce_top2_kernel(
    const float* __restrict__ bias, float* __restrict__ outR)
{
    const int m = blockIdx.x;
    const int tid = threadIdx.x;

    float v1 = -CUDART_INF_F, v2 = -CUDART_INF_F;
    int   i1 = 0x7fffffff,   i2 = 0x7fffffff;

#pragma unroll
    for (int it = 0; it < 4; it++) {
        int n = tid + it * 256;
        if (n >= COUT) break;
        float s = bias[n];
#pragma unroll
        for (int ks = 0; ks < KSPLIT; ks++)
            s += g_partial[(size_t)ks * BATCH * NPAD + (size_t)m * NPAD + n];
        outR[m * COUT + n] = s;
        if (s > v1 || (s == v1 && n < i1)) { v2 = v1; i2 = i1; v1 = s; i1 = n; }
        else if (s > v2 || (s == v2 && n < i2)) { v2 = s; i2 = n; }
    }

    __shared__ float sv1[256], sv2[256];
    __shared__ int   si1[256], si2[256];
    sv1[tid] = v1; si1[tid] = i1; sv2[tid] = v2; si2[tid] = i2;
    __syncthreads();

    for (int s = 128; s > 0; s >>= 1) {
        if (tid < s) {
            float a1 = sv1[tid],   a2 = sv2[tid];
            int   b1 = si1[tid],   b2 = si2[tid];
            float w1 = sv1[tid+s], w2 = sv2[tid+s];
            int   j1 = si1[tid+s], j2 = si2[tid+s];
            float r1, r2; int q1, q2;
            if (w1 > a1 || (w1 == a1 && j1 < b1)) {
                r1 = w1; q1 = j1;
                if (a1 > w2 || (a1 == w2 && b1 < j2)) { r2 = a1; q2 = b1; }
                else                                   { r2 = w2; q2 = j2; }
            } else {
                r1 = a1; q1 = b1;
                if (w1 > a2 || (w1 == a2 && j1 < b2)) { r2 = w1; q2 = j1; }
                else                                   { r2 = a2; q2 = b2; }
            }
            sv1[tid] = r1; si1[tid] = q1; sv2[tid] = r2; si2[tid] = q2;
        }
        __syncthreads();
    }
    if (tid == 0) {
        g_top2[m * 2 + 0] = si1[0];
        g_top2[m * 2 + 1] = si2[0];
    }
}

// ---------------------------------------------------------------------------
// Kernel 3: SPD path via B = S_n * A_stack  (per-n GEMM), double-buffered.
// A_stack[d, j]: j in [0,49) -> w0[d*49+j]; j in [64,113) -> w1[d*49+j-64].
// B[c,j] = sum_d S[n][c][d] * A_stack[d,j]     (M=128 c-tile, N=128, K=512)
// out[k,m] = sum_{c,hw} A_m[c,hw] * B[c, k-block + hw]
// grid (4 c-tiles, 256 n), 256 thr, warps 2(c) x 4(j).
// ---------------------------------------------------------------------------
#define SSTR 72
#define STILE (128 * SSTR * 2)        // 18432 B
#define OFF_A (4 * STILE)             // 73728
#define SPD_SMEM (8 * STILE)          // 147456
#define AFSTR 100

__global__ __launch_bounds__(256) void spd_mma_kernel(
    const float* __restrict__ SPD, const float* __restrict__ W)
{
    extern __shared__ char sm[];

    const int t = threadIdx.x;
    const int lane = t & 31, wid = t >> 5;
    const int wr = wid >> 2, ws = wid & 3;
    const int g = lane >> 2, tg = lane & 3;

    const int n  = blockIdx.y;
    const int c0 = blockIdx.x * 128;

    const int o0 = g_top2[n * 2 + 0];
    const int o1 = g_top2[n * 2 + 1];
    const float* w0 = W + (size_t)o0 * KD;
    const float* w1 = W + (size_t)o1 * KD;
    const float* Sn = SPD + (size_t)n * CIN * CIN;

    // zero-pad rows 49..63 and 113..127 of both A buffers (hi & lo) once
    for (int idx = t; idx < 30 * 64; idx += 256) {
        int r = idx >> 6;
        int col = idx & 63;
        int row = (r < 15) ? (49 + r) : (113 + r - 15);
#pragma unroll
        for (int buf = 0; buf < 2; buf++) {
            __nv_bfloat16* Bh = (__nv_bfloat16*)(sm + OFF_A + buf * 2 * STILE);
            __nv_bfloat16* Bl = (__nv_bfloat16*)(sm + OFF_A + buf * 2 * STILE + STILE);
            Bh[row * SSTR + col] = __float2bfloat16(0.f);
            Bl[row * SSTR + col] = __float2bfloat16(0.f);
        }
    }

    float acc[4][4][4];
#pragma unroll
    for (int a = 0; a < 4; a++)
#pragma unroll
        for (int b = 0; b < 4; b++)
#pragma unroll
            for (int c = 0; c < 4; c++) acc[a][b][c] = 0.f;

    float4 ps[8];
    float  pw0[13], pw1[13];

    auto loadchunk = [&](int ch) {
        int dch = ch * 64;
#pragma unroll
        for (int i = 0; i < 8; i++) {
            int idx = t + i * 256;
            int c = idx >> 4, q = idx & 15;
            ps[i] = *(const float4*)(Sn + (size_t)(c0 + c) * CIN + dch + q * 4);
        }
#pragma unroll
        for (int i = 0; i < 13; i++) {
            int idx = t + i * 256;
            if (idx < 3136) {
                pw0[i] = w0[dch * KHW + idx];
                pw1[i] = w1[dch * KHW + idx];
            }
        }
    };
    auto storechunk = [&](int buf) {
        __nv_bfloat16* Sh = (__nv_bfloat16*)(sm + buf * 2 * STILE);
        __nv_bfloat16* Sl = (__nv_bfloat16*)(sm + buf * 2 * STILE + STILE);
        __nv_bfloat16* Bh = (__nv_bfloat16*)(sm + OFF_A + buf * 2 * STILE);
        __nv_bfloat16* Bl = (__nv_bfloat16*)(sm + OFF_A + buf * 2 * STILE + STILE);
#pragma unroll
        for (int i = 0; i < 8; i++) {
            int idx = t + i * 256;
            int c = idx >> 4, q = idx & 15;
            int base = c * SSTR + q * 4;
            const float v[4] = {ps[i].x, ps[i].y, ps[i].z, ps[i].w};
#pragma unroll
            for (int j = 0; j < 4; j++) {
                __nv_bfloat16 h, l;
                bsplit(v[j], h, l);
                Sh[base + j] = h; Sl[base + j] = l;
            }
        }
#pragma unroll
        for (int i = 0; i < 13; i++) {
            int idx = t + i * 256;
            if (idx < 3136) {
                int dd = idx / KHW;
                int hw = idx - dd * KHW;
                __nv_bfloat16 h, l;
                bsplit(pw0[i], h, l);
                Bh[hw * SSTR + dd] = h;        Bl[hw * SSTR + dd] = l;
                bsplit(pw1[i], h, l);
                Bh[(64 + hw) * SSTR + dd] = h; Bl[(64 + hw) * SSTR + dd] = l;
            }
        }
    };

    loadchunk(0);
    storechunk(0);
    loadchunk(1);
    __syncthreads();

    for (int ch = 0; ch < 8; ch++) {
        if (ch + 1 < 8) storechunk((ch + 1) & 1);
        if (ch + 2 < 8) loadchunk(ch + 2);

        const __nv_bfloat16* Sh = (const __nv_bfloat16*)(sm + (ch & 1) * 2 * STILE);
        const __nv_bfloat16* Sl = (const __nv_bfloat16*)(sm + (ch & 1) * 2 * STILE + STILE);
        const __nv_bfloat16* Bh = (const __nv_bfloat16*)(sm + OFF_A + (ch & 1) * 2 * STILE);
        const __nv_bfloat16* Bl = (const __nv_bfloat16*)(sm + OFF_A + (ch & 1) * 2 * STILE + STILE);

#pragma unroll
        for (int ks = 0; ks < 4; ks++) {
            const int kb = ks * 16;
            unsigned bh[4][2], bl[4][2];
#pragma unroll
            for (int ni = 0; ni < 4; ni++) {
                int jr = ws * 32 + ni * 8 + g;
                int base = jr * SSTR + kb + tg * 2;
                bh[ni][0] = U32S(&Bh[base]);  bh[ni][1] = U32S(&Bh[base + 8]);
                bl[ni][0] = U32S(&Bl[base]);  bl[ni][1] = U32S(&Bl[base + 8]);
            }
#pragma unroll
            for (int mi = 0; mi < 4; mi++) {
                int cr = wr * 64 + mi * 16 + g;
                int base = cr * SSTR + kb + tg * 2;
                unsigned ah[4], al[4];
                ah[0] = U32S(&Sh[base]);       ah[1] = U32S(&Sh[base + 8 * SSTR]);
                ah[2] = U32S(&Sh[base + 8]);   ah[3] = U32S(&Sh[base + 8 * SSTR + 8]);
                al[0] = U32S(&Sl[base]);       al[1] = U32S(&Sl[base + 8 * SSTR]);
                al[2] = U32S(&Sl[base + 8]);   al[3] = U32S(&Sl[base + 8 * SSTR + 8]);
#pragma unroll
                for (int ni = 0; ni < 4; ni++) {
                    mma16816(acc[mi][ni], ah, bh[ni]);
                    mma16816(acc[mi][ni], ah, bl[ni]);
                    mma16816(acc[mi][ni], al, bh[ni]);
                }
            }
        }
        __syncthreads();
    }

    // stage Af[c][m*49+hw] fp32 for the fold (aliases S buffers)
    float* Af = (float*)sm;
    for (int idx = t; idx < 6272; idx += 256) {
        int c  = idx / KHW;
        int hw = idx - c * KHW;
        Af[c * AFSTR + hw]       = w0[c0 * KHW + idx];
        Af[c * AFSTR + KHW + hw] = w1[c0 * KHW + idx];
    }
    __syncthreads();

    float p00 = 0.f, p01 = 0.f, p10 = 0.f, p11 = 0.f;
#pragma unroll
    for (int mi = 0; mi < 4; mi++)
#pragma unroll
        for (int ni = 0; ni < 4; ni++)
#pragma unroll
            for (int v = 0; v < 4; v++) {
                int c = wr * 64 + mi * 16 + g + ((v >= 2) ? 8 : 0);
                int j = ws * 32 + ni * 8 + tg * 2 + (v & 1);
                float bv = acc[mi][ni][v];
                if (j < KHW) {
                    p00 += Af[c * AFSTR + j] * bv;
                    p01 += Af[c * AFSTR + KHW + j] * bv;
                } else if (j >= 64 && j < 64 + KHW) {
                    int hw = j - 64;
                    p10 += Af[c * AFSTR + hw] * bv;
                    p11 += Af[c * AFSTR + KHW + hw] * bv;
                }
            }

    __syncthreads();
    float* red = (float*)(sm + OFF_A);
    red[0 * 256 + t] = p00;
    red[1 * 256 + t] = p01;
    red[2 * 256 + t] = p10;
    red[3 * 256 + t] = p11;
    __syncthreads();
    for (int s = 128; s > 0; s >>= 1) {
        if (t < s) {
#pragma unroll
            for (int q = 0; q < 4; q++)
                red[q * 256 + t] += red[q * 256 + t + s];
        }
        __syncthreads();
    }
    if (t == 0) {
#pragma unroll
        for (int q = 0; q < 4; q++)
            g_spd_part[(n * 4 + blockIdx.x) * 4 + q] = red[q * 256];
    }
}

// ---------------------------------------------------------------------------
// Kernel 4: reduce SPD partials over c-tiles -> outSPD
// ---------------------------------------------------------------------------
__global__ void spd_reduce_kernel(float* __restrict__ outSPD)
{
    int i = blockIdx.x * 256 + threadIdx.x;
    if (i >= BATCH * 4) return;
    int n = i >> 2, q = i & 3;
    float s = 0.f;
#pragma unroll
    for (int dt = 0; dt < 4; dt++)
        s += g_spd_part[(n * 4 + dt) * 4 + q];
    outSPD[i] = s;
}

// ---------------------------------------------------------------------------
extern "C" void kernel_launch(void* const* d_in, const int* in_sizes, int n_in,
                              void* d_out, int out_size)
{
    const float* inputR   = (const float*)d_in[0];   // [256,512,7,7]
    const float* inputSPD = (const float*)d_in[1];   // [256,512,512]
    const float* weight   = (const float*)d_in[2];   // [1000,512,7,7]
    const float* bias     = (const float*)d_in[3];   // [1000]
    float* out = (float*)d_out;

    cudaFuncSetAttribute(gemm_mma_kernel,
                         cudaFuncAttributeMaxDynamicSharedMemorySize, GEMM_SMEM);
    cudaFuncSetAttribute(spd_mma_kernel,
                         cudaFuncAttributeMaxDynamicSharedMemorySize, SPD_SMEM);

    // 1) FC GEMM (bf16-split tensor cores, double-buffered), split-K partials
    gemm_mma_kernel<<<dim3(8, 2, KSPLIT), 256, GEMM_SMEM>>>(inputR, weight);

    // 2) fused reduce + bias + top-2
    reduce_top2_kernel<<<BATCH, 256>>>(bias, out);

    // 3) SPD path: B = S*A_stack per sample, fold against weights
    spd_mma_kernel<<<dim3(4, BATCH), 256, SPD_SMEM>>>(inputSPD, weight);

    // 4) reduce SPD partials
    spd_reduce_kernel<<<4, 256>>>(out + BATCH * COUT);
}